// round 17
// baseline (speedup 1.0000x reference)
#include <cuda_runtime.h>
#include <cuda_fp16.h>
#include <math.h>
#include <stdint.h>

#define NROWS 4096
#define TWO_N 8192
#define D 128
#define NTILE 64
#define NJOBS 2080                  // 64*65/2 triangle tiles
#define GRID_MAIN 444               // 3 CTAs per SM
#define CTA_T 128                   // 4 warps, 2x2 grid of 64x64 warp tiles
#define PSC 3.798282565009841f      // sqrt(10/ln2) pre-scale
#define NEG_C2 0xCB37CB37u          // packed f16x2 (-C,-C), C = 14.4296875 (f16-exact)
#define TAIL_C 10.00189733f         // C * ln(2)
#define DIAG_F 0.99810459f          // exact diag term e^(10 - TAIL_C)

// ---------------- device scratch (allocation-free) ----------------
__device__ __half         g_h[TWO_N * D];
__device__ float          g_pos[TWO_N];
__device__ float          g_part[TWO_N * NTILE];   // [row][J] -- coalesced tail reads
__device__ float          g_bsum[32];
__device__ unsigned int   g_cnt;                   // tail arrival counter
__device__ unsigned int   g_job;                   // dynamic job counter (reset by k_tail)

// ---------------- smem map (dynamic): 69632 B/CTA -> 3 CTAs/SM ----------------
#define SM_A      0
#define SM_B      32768
#define SM_RED(b) (65536 + (b) * 2048)     // rowred[128][2] + colred[128][2]
#define SMEM_BYTES 69632

// ---------------- helpers ----------------
__device__ __forceinline__ uint32_t smem_u32(const void* p) {
    uint32_t a;
    asm("{ .reg .u64 t; cvta.to.shared.u64 t, %1; cvt.u32.u64 %0, t; }" : "=r"(a) : "l"(p));
    return a;
}
__device__ __forceinline__ void ex2_h2_ip(uint32_t& x) {
    asm volatile("ex2.approx.f16x2 %0, %0;" : "+r"(x));
}
__device__ __forceinline__ uint32_t hadd2(uint32_t a, uint32_t b) {
    uint32_t r; asm("add.rn.f16x2 %0, %1, %2;" : "=r"(r) : "r"(a), "r"(b)); return r;
}
__device__ __forceinline__ float h2_low(uint32_t v)  { __half2 h = *(__half2*)&v; return __low2float(h); }
__device__ __forceinline__ float h2_high(uint32_t v) { __half2 h = *(__half2*)&v; return __high2float(h); }
__device__ __forceinline__ void ldsm4(uint32_t* r, uint32_t addr) {
    asm volatile("ldmatrix.sync.aligned.m8n8.x4.shared.b16 {%0,%1,%2,%3}, [%4];"
                 : "=r"(r[0]), "=r"(r[1]), "=r"(r[2]), "=r"(r[3]) : "r"(addr));
}
__device__ __forceinline__ void mma_h(uint32_t* d, const uint32_t* a, uint32_t b0, uint32_t b1) {
    asm volatile("mma.sync.aligned.m16n8k16.row.col.f16.f16.f16.f16 "
                 "{%0,%1}, {%2,%3,%4,%5}, {%6,%7}, {%0,%1};"
                 : "+r"(d[0]), "+r"(d[1])
                 : "r"(a[0]), "r"(a[1]), "r"(a[2]), "r"(a[3]), "r"(b0), "r"(b1));
}
#define CP_ASYNC16(sa, ga) \
    asm volatile("cp.async.cg.shared.global [%0], [%1], 16;" :: "r"(sa), "l"(ga))
#define CP_COMMIT() asm volatile("cp.async.commit_group;" ::: "memory")
#define CP_WAIT0()  asm volatile("cp.async.wait_group 0;" ::: "memory")

// closed-form triangle job -> (I, J): off(i) = i*(129-i)/2
__device__ __forceinline__ void job_from(int g, int& I, int& J) {
    int i = (int)((129.0f - sqrtf(16641.0f - 8.0f * (float)g)) * 0.5f);
    if (i > 63) i = 63;
    if (i < 0) i = 0;
    while (i > 0 && i * (129 - i) / 2 > g) i--;
    while (i < 63 && (i + 1) * (128 - i) / 2 <= g) i++;
    I = i; J = i + (g - i * (129 - i) / 2);
}

// ---------------------------------------------------------------------------
// Kernel 1: normalize + pre-scale + fp16 cast + fp32-exact positives.
// ---------------------------------------------------------------------------
__global__ void k_prep(const float* __restrict__ zi, const float* __restrict__ zj) {
    int warp = threadIdx.x >> 5, lane = threadIdx.x & 31;
    int p = blockIdx.x * 8 + warp;
    float4 a = ((const float4*)(zi + (size_t)p * D))[lane];
    float4 b = ((const float4*)(zj + (size_t)p * D))[lane];
    float sa = a.x*a.x + a.y*a.y + a.z*a.z + a.w*a.w;
    float sb = b.x*b.x + b.y*b.y + b.z*b.z + b.w*b.w;
    float dp = a.x*b.x + a.y*b.y + a.z*b.z + a.w*b.w;
    #pragma unroll
    for (int o = 16; o; o >>= 1) {
        sa += __shfl_xor_sync(0xffffffffu, sa, o);
        sb += __shfl_xor_sync(0xffffffffu, sb, o);
        dp += __shfl_xor_sync(0xffffffffu, dp, o);
    }
    float ia = 1.0f / fmaxf(sqrtf(sa), 1e-8f);
    float ib = 1.0f / fmaxf(sqrtf(sb), 1e-8f);
    if (lane == 0) {
        float pos = dp * ia * ib;
        g_pos[p] = pos;
        g_pos[p + NROWS] = pos;
    }
    float fa = ia * PSC, fb = ib * PSC;
    __half ha[4], hb[4];
    ha[0] = __float2half(a.x*fa); ha[1] = __float2half(a.y*fa);
    ha[2] = __float2half(a.z*fa); ha[3] = __float2half(a.w*fa);
    hb[0] = __float2half(b.x*fb); hb[1] = __float2half(b.y*fb);
    hb[2] = __float2half(b.z*fb); hb[3] = __float2half(b.w*fb);
    *(uint2*)(g_h + (size_t)p * D + lane * 4)           = *(uint2*)ha;
    *(uint2*)(g_h + (size_t)(p + NROWS) * D + lane * 4) = *(uint2*)hb;
}

// ---------------- async tile loaders (XOR-swizzled 16B chunks, 256B rows) ----
__device__ __forceinline__ void load_tile_async(uint32_t sb, uint32_t off, int rowBase, int t) {
    #pragma unroll
    for (int rep = 0; rep < 16; rep++) {
        int idx = rep * CTA_T + t;        // 0..2047
        int row = idx >> 4, ch = idx & 15;
        uint32_t so = off + (uint32_t)(row * 256) + ((uint32_t)(ch ^ (row & 7)) << 4);
        CP_ASYNC16(sb + so, g_h + (size_t)(rowBase + row) * D + ch * 8);
    }
}

// ---------------------------------------------------------------------------
// tile body: 64x64 warp tile (mt 4 x nt 8), f16 accumulate
// ---------------------------------------------------------------------------
__device__ __forceinline__ void tile_body(
    uint32_t (&d)[4][8][2], uint32_t bBase,
    const uint32_t (&aRow)[4], const uint32_t (&bRow)[4],
    int c4A, int c4B, int r7)
{
    #pragma unroll
    for (int mt = 0; mt < 4; mt++)
        #pragma unroll
        for (int nt = 0; nt < 8; nt++) { d[mt][nt][0] = NEG_C2; d[mt][nt][1] = NEG_C2; }

    #pragma unroll
    for (int ks = 0; ks < 8; ks++) {
        uint32_t ah[4][4], bh[16];
        const uint32_t offA = (uint32_t)(((2 * ks + c4A) ^ r7) << 4);
        const uint32_t offB = (uint32_t)(((2 * ks + c4B) ^ r7) << 4);
        #pragma unroll
        for (int mt = 0; mt < 4; mt++) ldsm4(ah[mt], aRow[mt] + offA);
        #pragma unroll
        for (int g = 0; g < 4; g++) ldsm4(bh + g * 4, bBase + bRow[g] + offB);
        #pragma unroll
        for (int mt = 0; mt < 4; mt++)
            #pragma unroll
            for (int nt = 0; nt < 8; nt++)
                mma_h(d[mt][nt], ah[mt], bh[nt * 2], bh[nt * 2 + 1]);
    }
}

// epilogue: ex2 + exact-diag substitute + row/col trees -> red[par]
__device__ __forceinline__ void epi_reduce(
    char* sm, uint32_t (&d)[4][8][2], int par, int Ie, int Je,
    int lane, int warpM, int warpN, int rq, int cq, uint32_t DIAG_H16)
{
    #pragma unroll
    for (int mt = 0; mt < 4; mt++)
        #pragma unroll
        for (int nt = 0; nt < 8; nt++) {
            ex2_h2_ip(d[mt][nt][0]);
            ex2_h2_ip(d[mt][nt][1]);
        }
    if (Ie == Je) {
        #pragma unroll
        for (int mt = 0; mt < 4; mt++) {
            #pragma unroll
            for (int q = 0; q < 2; q++) {
                const int r = warpM * 64 + mt * 16 + q * 8 + rq;
                #pragma unroll
                for (int nt = 0; nt < 8; nt++) {
                    const int c0 = warpN * 64 + nt * 8 + cq;
                    if (r == c0)     d[mt][nt][q] = (d[mt][nt][q] & 0xFFFF0000u) | DIAG_H16;
                    if (r == c0 + 1) d[mt][nt][q] = (d[mt][nt][q] & 0x0000FFFFu) | (DIAG_H16 << 16);
                }
            }
        }
    }
    float* rowred = (float*)(sm + SM_RED(par));            // [128][2]
    float* colred = (float*)(sm + SM_RED(par) + 1024);     // [128][2]
    #pragma unroll
    for (int mt = 0; mt < 4; mt++) {
        #pragma unroll
        for (int q = 0; q < 2; q++) {
            uint32_t p0 = hadd2(d[mt][0][q], d[mt][1][q]);
            uint32_t p1 = hadd2(d[mt][2][q], d[mt][3][q]);
            uint32_t p2 = hadd2(d[mt][4][q], d[mt][5][q]);
            uint32_t p3 = hadd2(d[mt][6][q], d[mt][7][q]);
            uint32_t rp = hadd2(hadd2(p0, p1), hadd2(p2, p3));
            float v = h2_low(rp) + h2_high(rp);
            v += __shfl_xor_sync(0xffffffffu, v, 1);
            v += __shfl_xor_sync(0xffffffffu, v, 2);
            if ((lane & 3) == 0) {
                int r = warpM * 64 + mt * 16 + q * 8 + rq;
                rowred[r * 2 + warpN] = v;
            }
        }
    }
    #pragma unroll
    for (int nt = 0; nt < 8; nt++) {
        uint32_t cp = hadd2(hadd2(hadd2(d[0][nt][0], d[0][nt][1]),
                                  hadd2(d[1][nt][0], d[1][nt][1])),
                            hadd2(hadd2(d[2][nt][0], d[2][nt][1]),
                                  hadd2(d[3][nt][0], d[3][nt][1])));
        cp = hadd2(cp, (uint32_t)__shfl_xor_sync(0xffffffffu, (int)cp, 4));
        cp = hadd2(cp, (uint32_t)__shfl_xor_sync(0xffffffffu, (int)cp, 8));
        cp = hadd2(cp, (uint32_t)__shfl_xor_sync(0xffffffffu, (int)cp, 16));
        if (lane < 4) {
            int c0 = warpN * 64 + nt * 8 + (lane & 3) * 2;
            colred[c0 * 2 + warpM]       = h2_low(cp);
            colred[(c0 + 1) * 2 + warpM] = h2_high(cp);
        }
    }
}
__device__ __forceinline__ void epi_write(char* sm, int par, int Ie, int Je, int t) {
    float* rowred = (float*)(sm + SM_RED(par));
    float* colred = (float*)(sm + SM_RED(par) + 1024);
    float s = rowred[t * 2] + rowred[t * 2 + 1];
    g_part[((size_t)(Ie * 128 + t)) * 64 + Je] = s;
    if (Je > Ie) {
        float c = colred[t * 2] + colred[t * 2 + 1];
        g_part[((size_t)(Je * 128 + t)) * 64 + Ie] = c;
    }
}

// ---------------------------------------------------------------------------
// Kernel 2: triangle sim-GEMM; 444 CTAs x 128 threads (3 CTAs/SM),
// dynamic work-stealing (two-ahead fetch), fully-async A/B prefetch.
// ---------------------------------------------------------------------------
__global__ __launch_bounds__(CTA_T, 3)
void k_main() {
    extern __shared__ char sm[];
    static __shared__ int s_job[2];
    const uint32_t sb = smem_u32(sm);
    const int t = threadIdx.x, lane = t & 31, wid = t >> 5;
    const int warpM = wid >> 1, warpN = wid & 1;   // 2 x 2 warp grid

    const __half diag_h = __float2half(DIAG_F);
    const uint32_t DIAG_H16 = (uint32_t)*(const uint16_t*)&diag_h;

    const int r7   = lane & 7;
    const int rowA = (lane & 7) + ((lane >> 3) & 1) * 8;  const int c4A = lane >> 4;
    const int rowB = (lane & 7) + ((lane >> 4) << 3);     const int c4B = (lane >> 3) & 1;
    const int rq = lane >> 2;
    const int cq = (lane & 3) * 2;

    uint32_t aRow[4];
    #pragma unroll
    for (int mt = 0; mt < 4; mt++)
        aRow[mt] = sb + SM_A + (uint32_t)((warpM * 64 + mt * 16 + rowA) * 256);
    uint32_t bRow[4];
    #pragma unroll
    for (int g = 0; g < 4; g++)
        bRow[g] = (uint32_t)((warpN * 64 + g * 16 + rowB) * 256);

    uint32_t d[4][8][2];

    // prologue: fetch job 0, issue its loads, fetch job 1 id
    if (t == 0) s_job[0] = (int)atomicAdd(&g_job, 1u);
    __syncthreads();
    int jc = s_job[0];
    if (jc >= NJOBS) return;
    int Ic, Jc; job_from(jc, Ic, Jc);
    load_tile_async(sb, SM_A, Ic * 128, t);
    load_tile_async(sb, SM_B, Jc * 128, t);
    CP_COMMIT();
    if (t == 0) s_job[1] = (int)atomicAdd(&g_job, 1u);

    int k = 0;
    bool havePrev = false;
    int pI = 0, pJ = 0;

    while (true) {
        CP_WAIT0();
        __syncthreads();                       // A/B ready; s_job[(k+1)&1] visible; red[(k-1)&1] done
        if (havePrev) epi_write(sm, (k ^ 1) & 1, pI, pJ, t);
        tile_body(d, sb + SM_B, aRow, bRow, c4A, c4B, r7);
        __syncthreads();                       // all warps done reading A/B

        const int jn = s_job[(k + 1) & 1];
        const bool more = (jn < NJOBS);
        int In = 0, Jn = 0;
        if (more) {
            job_from(jn, In, Jn);
            if (In != Ic) load_tile_async(sb, SM_A, In * 128, t);
            load_tile_async(sb, SM_B, Jn * 128, t);
        }
        CP_COMMIT();
        if (t == 0 && more) s_job[k & 1] = (int)atomicAdd(&g_job, 1u);

        epi_reduce(sm, d, k & 1, Ic, Jc, lane, warpM, warpN, rq, cq, DIAG_H16);
        pI = Ic; pJ = Jc; havePrev = true;
        if (!more) break;
        Ic = In; Jc = Jn; k++;
    }
    __syncthreads();
    epi_write(sm, k & 1, pI, pJ, t);
}

// ---------------------------------------------------------------------------
// Kernel 3: per-row loss (coalesced float4 reads) + reduction + counter reset.
// ---------------------------------------------------------------------------
__global__ void k_tail(float* __restrict__ out) {
    __shared__ float red[256];
    __shared__ bool isLast;
    int r = blockIdx.x * 256 + threadIdx.x;
    const float4* base = (const float4*)(g_part + (size_t)r * 64);
    float S = 0.0f;
    #pragma unroll
    for (int q = 0; q < 16; q++) {
        float4 v = base[q];
        S += v.x + v.y + v.z + v.w;
    }
    float p = g_pos[r];
    float Sf = S + expf(fmaf(10.0f, p, -TAIL_C));
    red[threadIdx.x] = logf(Sf) + TAIL_C - 10.0f * p;
    __syncthreads();
    for (int s = 128; s; s >>= 1) {
        if (threadIdx.x < s) red[threadIdx.x] += red[threadIdx.x + s];
        __syncthreads();
    }
    if (threadIdx.x == 0) {
        g_bsum[blockIdx.x] = red[0];
        __threadfence();
        unsigned int done = atomicAdd(&g_cnt, 1u);
        isLast = (done == 31u);
    }
    __syncthreads();
    if (isLast && threadIdx.x == 0) {
        float acc = 0.0f;
        #pragma unroll
        for (int b = 0; b < 32; b++) acc += ((volatile float*)g_bsum)[b];
        out[0] = acc * (1.0f / (float)TWO_N);
        g_cnt = 0;
        g_job = 0;   // reset work-stealing counter for next graph replay
    }
}

// ---------------------------------------------------------------------------
extern "C" void kernel_launch(void* const* d_in, const int* in_sizes, int n_in,
                              void* d_out, int out_size) {
    const float* zi = (const float*)d_in[0];
    const float* zj = (const float*)d_in[1];
    float* out = (float*)d_out;

    cudaFuncSetAttribute(k_main, cudaFuncAttributeMaxDynamicSharedMemorySize, SMEM_BYTES);

    k_prep<<<512, 256>>>(zi, zj);
    k_main<<<GRID_MAIN, CTA_T, SMEM_BYTES>>>();
    k_tail<<<32, 256>>>(out);
}